// round 1
// baseline (speedup 1.0000x reference)
#include <cuda_runtime.h>
#include <math.h>

// ---------------------------------------------------------------------------
// FusedHybridBlock: RMSNorm -> dual GEMM(delta,b)+nonlin -> liquid+PLIF scan
//                   -> dual GEMM(syn,gate)+residual -> RMSNorm
//                   -> dual GEMM(ffn gate,up)+SiLU -> GEMM(down)+residual
// B=8, T=2048, D=1024, DFF=4096, M = B*T = 16384. All fp32.
// GEMM microkernel uses packed fma.rn.f32x2 (FFMA2) for 2x fp32 throughput.
// ---------------------------------------------------------------------------

typedef unsigned long long ull;

#define BM 128
#define BN 128
#define BKT 8
#define NTHREADS 256

static const int Mdim = 16384;
static const int Ddim = 1024;
static const int Fdim = 4096;
static const int Tdim = 2048;

// Scratch (device globals; allocation in kernel_launch is forbidden)
__device__ float g_y  [16384 * 1024];   // y1, then reused as y2
__device__ float g_Aa [16384 * 1024];   // A = exp(-delta*exp(A_log))
__device__ float g_Bb [16384 * 1024];   // bvec
__device__ float g_sp [16384 * 1024];   // spike_in = spike + h_post
__device__ float g_x1 [16384 * 1024];   // x1
__device__ float g_act[16384 * 4096];   // silu(g)*u

// ---- f32x2 helpers --------------------------------------------------------
__device__ __forceinline__ ull pk2(float lo, float hi) {
    ull r; asm("mov.b64 %0, {%1, %2};" : "=l"(r) : "f"(lo), "f"(hi)); return r;
}
__device__ __forceinline__ void fma2(ull& d, ull a, ull b) {
    asm("fma.rn.f32x2 %0, %1, %2, %0;" : "+l"(d) : "l"(a), "l"(b));
}
__device__ __forceinline__ float2 up2(ull v) {
    float2 r; asm("mov.b64 {%0, %1}, %2;" : "=f"(r.x), "=f"(r.y) : "l"(v)); return r;
}
__device__ __forceinline__ float softplusf(float v) {
    return fmaxf(v, 0.f) + log1pf(expf(-fabsf(v)));
}
__device__ __forceinline__ float sigmoidf(float v) {
    return 1.f / (1.f + expf(-v));
}

// ---- RMSNorm: one block per row, D=1024 -----------------------------------
__global__ void rmsnorm_kernel(const float* __restrict__ x,
                               const float* __restrict__ w,
                               float* __restrict__ y) {
    const int row = blockIdx.x;
    const int t = threadIdx.x;               // 256 threads, 1 float4 each
    const float4* xr = (const float4*)(x + (size_t)row * 1024);
    const float4* wr = (const float4*)w;
    float4 v = xr[t];
    float ss = v.x * v.x + v.y * v.y + v.z * v.z + v.w * v.w;
    #pragma unroll
    for (int off = 16; off > 0; off >>= 1)
        ss += __shfl_xor_sync(0xffffffffu, ss, off);
    __shared__ float red[8];
    if ((t & 31) == 0) red[t >> 5] = ss;
    __syncthreads();
    float tot = red[0] + red[1] + red[2] + red[3] + red[4] + red[5] + red[6] + red[7];
    float rstd = rsqrtf(tot * (1.f / 1024.f) + 1e-6f);
    float4 wv = wr[t];
    float4 o;
    o.x = v.x * rstd * wv.x; o.y = v.y * rstd * wv.y;
    o.z = v.z * rstd * wv.z; o.w = v.w * rstd * wv.w;
    ((float4*)(y + (size_t)row * 1024))[t] = o;
}

// ---- liquid + PLIF sequential scan over T ---------------------------------
// one thread per (b,d) channel; 8192 channels; coalesced across d
__global__ void scan_kernel(const float* __restrict__ Ab,
                            const float* __restrict__ Bb,
                            const float* __restrict__ log_tau,
                            const float* __restrict__ thr,
                            float* __restrict__ spike_in) {
    const int gid = blockIdx.x * blockDim.x + threadIdx.x; // 0..8191
    const int d = gid & (Ddim - 1);
    const int b = gid >> 10;
    const float pdec = expf(-expf(-log_tau[d]));   // exp(-1/tau)
    const float omp  = 1.f - pdec;
    const float th   = thr[d];
    size_t idx = (size_t)b * Tdim * Ddim + d;
    float h = 0.f, v = 0.f;
    for (int t = 0; t < Tdim; ++t, idx += Ddim) {
        float a  = Ab[idx];
        float bb = Bb[idx];
        h = tanhf(fmaf(a, h, bb));
        float vpre = fmaf(pdec, v, omp * h);
        float s = (vpre > th) ? 1.f : 0.f;
        v = vpre - s * th;
        spike_in[idx] = s + h;
    }
}

// ---- fused (dual-)GEMM: out[m,n] = sum_k A[m,k]*W{1,2}[n,k], epilogue EPI --
// EPI 0: out1=exp(-softplus(c1+b1)*exp(A_log[n])), out2=softplus(c1+b1)*(c2+b2)
// EPI 1: out1 = extra(x) + (c1+b1)*sigmoid(c2+b2)           (x1)
// EPI 2: out1 = c1*sigmoid(c1)*c2                           (silu(g)*u)
// EPI 3: out1 = extra(x1) + c1                              (down + residual)
template <bool DUAL, int EPI>
__global__ void __launch_bounds__(NTHREADS, 1)
gemm_kernel(const float* __restrict__ A,
            const float* __restrict__ W1,
            const float* __restrict__ W2,
            float* __restrict__ out1,
            float* __restrict__ out2,
            const float* __restrict__ bias1,
            const float* __restrict__ bias2,
            const float* __restrict__ extra,
            int M, int N, int K) {
    __shared__ float As [2][BKT][BM];
    __shared__ float Bs1[2][BKT][BN];
    __shared__ float Bs2[2][BKT][BN];

    const int tid = threadIdx.x;
    const int bm = blockIdx.y * BM;
    const int bn = blockIdx.x * BN;

    // global->smem loader coords: 1 float4 per matrix per thread
    const int lr = tid >> 1;            // 0..127
    const int lc = (tid & 1) * 4;       // 0 or 4

    const float* Ap  = A  + (size_t)(bm + lr) * K + lc;
    const float* W1p = W1 + (size_t)(bn + lr) * K + lc;
    const float* W2p = DUAL ? (W2 + (size_t)(bn + lr) * K + lc) : W1;

    // compute coords: 16x16 thread grid, 8x8 outputs each
    const int tx = tid & 15;
    const int ty = tid >> 4;
    const int tr = ty * 8;
    const int tc = tx * 8;

    ull acc1[8][4];
    ull acc2[8][4];
    #pragma unroll
    for (int i = 0; i < 8; i++)
        #pragma unroll
        for (int j = 0; j < 4; j++) { acc1[i][j] = 0ull; acc2[i][j] = 0ull; }

    // prologue: load k-tile 0
    float4 ra  = *(const float4*)Ap;
    float4 rb1 = *(const float4*)W1p;
    float4 rb2 = make_float4(0.f, 0.f, 0.f, 0.f);
    if (DUAL) rb2 = *(const float4*)W2p;
    As [0][lc + 0][lr] = ra.x;  As [0][lc + 1][lr] = ra.y;
    As [0][lc + 2][lr] = ra.z;  As [0][lc + 3][lr] = ra.w;
    Bs1[0][lc + 0][lr] = rb1.x; Bs1[0][lc + 1][lr] = rb1.y;
    Bs1[0][lc + 2][lr] = rb1.z; Bs1[0][lc + 3][lr] = rb1.w;
    if (DUAL) {
        Bs2[0][lc + 0][lr] = rb2.x; Bs2[0][lc + 1][lr] = rb2.y;
        Bs2[0][lc + 2][lr] = rb2.z; Bs2[0][lc + 3][lr] = rb2.w;
    }
    __syncthreads();

    const int nk = K / BKT;
    for (int kt = 0; kt < nk; ++kt) {
        const int cur = kt & 1;
        const int nxt = cur ^ 1;
        const bool more = (kt + 1 < nk);
        if (more) {
            const int ko = (kt + 1) * BKT;
            ra  = *(const float4*)(Ap  + ko);
            rb1 = *(const float4*)(W1p + ko);
            if (DUAL) rb2 = *(const float4*)(W2p + ko);
        }
        #pragma unroll
        for (int kk = 0; kk < BKT; ++kk) {
            float4 a0 = *(const float4*)&As[cur][kk][tr];
            float4 a1 = *(const float4*)&As[cur][kk][tr + 4];
            float4 b0 = *(const float4*)&Bs1[cur][kk][tc];
            float4 b1 = *(const float4*)&Bs1[cur][kk][tc + 4];
            ull vb[4];
            vb[0] = pk2(b0.x, b0.y); vb[1] = pk2(b0.z, b0.w);
            vb[2] = pk2(b1.x, b1.y); vb[3] = pk2(b1.z, b1.w);
            ull vc[4] = {0ull, 0ull, 0ull, 0ull};
            if (DUAL) {
                float4 c0 = *(const float4*)&Bs2[cur][kk][tc];
                float4 c1 = *(const float4*)&Bs2[cur][kk][tc + 4];
                vc[0] = pk2(c0.x, c0.y); vc[1] = pk2(c0.z, c0.w);
                vc[2] = pk2(c1.x, c1.y); vc[3] = pk2(c1.z, c1.w);
            }
            float av[8] = {a0.x, a0.y, a0.z, a0.w, a1.x, a1.y, a1.z, a1.w};
            #pragma unroll
            for (int i = 0; i < 8; i++) {
                ull ai = pk2(av[i], av[i]);
                fma2(acc1[i][0], ai, vb[0]);
                fma2(acc1[i][1], ai, vb[1]);
                fma2(acc1[i][2], ai, vb[2]);
                fma2(acc1[i][3], ai, vb[3]);
                if (DUAL) {
                    fma2(acc2[i][0], ai, vc[0]);
                    fma2(acc2[i][1], ai, vc[1]);
                    fma2(acc2[i][2], ai, vc[2]);
                    fma2(acc2[i][3], ai, vc[3]);
                }
            }
        }
        if (more) {
            As [nxt][lc + 0][lr] = ra.x;  As [nxt][lc + 1][lr] = ra.y;
            As [nxt][lc + 2][lr] = ra.z;  As [nxt][lc + 3][lr] = ra.w;
            Bs1[nxt][lc + 0][lr] = rb1.x; Bs1[nxt][lc + 1][lr] = rb1.y;
            Bs1[nxt][lc + 2][lr] = rb1.z; Bs1[nxt][lc + 3][lr] = rb1.w;
            if (DUAL) {
                Bs2[nxt][lc + 0][lr] = rb2.x; Bs2[nxt][lc + 1][lr] = rb2.y;
                Bs2[nxt][lc + 2][lr] = rb2.z; Bs2[nxt][lc + 3][lr] = rb2.w;
            }
            __syncthreads();
        }
    }

    // ------------------------------- epilogue -------------------------------
    const int gm = bm + tr;
    const int gn = bn + tc;
    float pb1[8], pb2[8], pea[8];
    if (EPI == 0 || EPI == 1) {
        #pragma unroll
        for (int j = 0; j < 8; j++) { pb1[j] = bias1[gn + j]; pb2[j] = bias2[gn + j]; }
    }
    if (EPI == 0) {
        #pragma unroll
        for (int j = 0; j < 8; j++) pea[j] = expf(extra[gn + j]);   // exp(A_log)
    }
    #pragma unroll
    for (int i = 0; i < 8; i++) {
        const size_t ro = (size_t)(gm + i) * N + gn;
        float c1[8], c2[8];
        #pragma unroll
        for (int j = 0; j < 4; j++) {
            float2 t = up2(acc1[i][j]); c1[2 * j] = t.x; c1[2 * j + 1] = t.y;
        }
        if (DUAL) {
            #pragma unroll
            for (int j = 0; j < 4; j++) {
                float2 t = up2(acc2[i][j]); c2[2 * j] = t.x; c2[2 * j + 1] = t.y;
            }
        }
        float o1[8], o2[8];
        if (EPI == 0) {
            #pragma unroll
            for (int j = 0; j < 8; j++) {
                float dl = softplusf(c1[j] + pb1[j]);
                o1[j] = expf(-dl * pea[j]);
                o2[j] = dl * (c2[j] + pb2[j]);
            }
        } else if (EPI == 1) {
            float4 xv0 = *(const float4*)(extra + ro);
            float4 xv1 = *(const float4*)(extra + ro + 4);
            float xv[8] = {xv0.x, xv0.y, xv0.z, xv0.w, xv1.x, xv1.y, xv1.z, xv1.w};
            #pragma unroll
            for (int j = 0; j < 8; j++)
                o1[j] = xv[j] + (c1[j] + pb1[j]) * sigmoidf(c2[j] + pb2[j]);
        } else if (EPI == 2) {
            #pragma unroll
            for (int j = 0; j < 8; j++)
                o1[j] = c1[j] * sigmoidf(c1[j]) * c2[j];
        } else {  // EPI == 3
            float4 xv0 = *(const float4*)(extra + ro);
            float4 xv1 = *(const float4*)(extra + ro + 4);
            float xv[8] = {xv0.x, xv0.y, xv0.z, xv0.w, xv1.x, xv1.y, xv1.z, xv1.w};
            #pragma unroll
            for (int j = 0; j < 8; j++)
                o1[j] = xv[j] + c1[j];
        }
        *(float4*)(out1 + ro)     = make_float4(o1[0], o1[1], o1[2], o1[3]);
        *(float4*)(out1 + ro + 4) = make_float4(o1[4], o1[5], o1[6], o1[7]);
        if (EPI == 0) {
            *(float4*)(out2 + ro)     = make_float4(o2[0], o2[1], o2[2], o2[3]);
            *(float4*)(out2 + ro + 4) = make_float4(o2[4], o2[5], o2[6], o2[7]);
        }
    }
}

// ---------------------------------------------------------------------------
extern "C" void kernel_launch(void* const* d_in, const int* in_sizes, int n_in,
                              void* d_out, int out_size) {
    // metadata order (setup_inputs): x, rms_w1, rms_w2, delta_w, delta_b,
    // b_w, b_b, A_log, log_tau, plif_thr, syn_w, syn_b, gate_w, gate_b,
    // ffn_g_w, ffn_u_w, ffn_d_w
    const float* x       = (const float*)d_in[0];
    const float* rms_w1  = (const float*)d_in[1];
    const float* rms_w2  = (const float*)d_in[2];
    const float* delta_w = (const float*)d_in[3];
    const float* delta_b = (const float*)d_in[4];
    const float* b_w     = (const float*)d_in[5];
    const float* b_b     = (const float*)d_in[6];
    const float* A_log   = (const float*)d_in[7];
    const float* log_tau = (const float*)d_in[8];
    const float* plif_thr= (const float*)d_in[9];
    const float* syn_w   = (const float*)d_in[10];
    const float* syn_b   = (const float*)d_in[11];
    const float* gate_w  = (const float*)d_in[12];
    const float* gate_b  = (const float*)d_in[13];
    const float* ffn_g_w = (const float*)d_in[14];
    const float* ffn_u_w = (const float*)d_in[15];
    const float* ffn_d_w = (const float*)d_in[16];
    float* out = (float*)d_out;

    float *y, *Aa, *Bb, *sp, *x1, *act;
    cudaGetSymbolAddress((void**)&y,   g_y);
    cudaGetSymbolAddress((void**)&Aa,  g_Aa);
    cudaGetSymbolAddress((void**)&Bb,  g_Bb);
    cudaGetSymbolAddress((void**)&sp,  g_sp);
    cudaGetSymbolAddress((void**)&x1,  g_x1);
    cudaGetSymbolAddress((void**)&act, g_act);

    const int M = Mdim, D = Ddim, F = Fdim;

    // 1) y1 = rmsnorm(x, w1)
    rmsnorm_kernel<<<M, 256>>>(x, rms_w1, y);

    // 2) A, bvec  (dual GEMM + softplus/exp epilogue)
    dim3 gDD(D / BN, M / BM);
    gemm_kernel<true, 0><<<gDD, NTHREADS>>>(y, delta_w, b_w, Aa, Bb,
                                            delta_b, b_b, A_log, M, D, D);

    // 3) liquid + PLIF scan -> spike_in
    scan_kernel<<<128, 64>>>(Aa, Bb, log_tau, plif_thr, sp);

    // 4) x1 = x + syn * sigmoid(gate)  (dual GEMM + fused epilogue)
    gemm_kernel<true, 1><<<gDD, NTHREADS>>>(sp, syn_w, gate_w, x1, nullptr,
                                            syn_b, gate_b, x, M, D, D);

    // 5) y2 = rmsnorm(x1, w2)
    rmsnorm_kernel<<<M, 256>>>(x1, rms_w2, y);

    // 6) act = silu(y2 @ g^T) * (y2 @ u^T)
    dim3 gDF(F / BN, M / BM);
    gemm_kernel<true, 2><<<gDF, NTHREADS>>>(y, ffn_g_w, ffn_u_w, act, nullptr,
                                            nullptr, nullptr, nullptr, M, F, D);

    // 7) out = x1 + act @ d^T
    gemm_kernel<false, 3><<<gDD, NTHREADS>>>(act, ffn_d_w, nullptr, out, nullptr,
                                             nullptr, nullptr, x1, M, D, F);
}

// round 3
// speedup vs baseline: 3.5244x; 3.5244x over previous
#include <cuda_runtime.h>
#include <math.h>
#include <stdint.h>

// ---------------------------------------------------------------------------
// FusedHybridBlock via mma.sync TF32 (base-arch tensor path; tcgen05 is not
// available because the harness compiles PTX at compute_103 without 'a').
//   RMSNorm -> dualGEMM(delta,b)+nonlin -> liquid+PLIF scan ->
//   dualGEMM(syn,gate)+residual -> RMSNorm -> dualGEMM(ffn g,u)+SiLU ->
//   GEMM(down)+residual
// GEMM: CTA 128x128, 512 thr / 16 warps, warp tile 32x32 (dual), BK=32,
// cp.async 3-stage pipeline, SW128 smem, ldmatrix.x4 fragments,
// mma.sync.m16n8k8.tf32. Operands RN-rounded to tf32.
// ---------------------------------------------------------------------------

#define NTHREADS   512
#define STAGE_A    16384
#define STAGE_BYTES 49152                      // A + B1 + B2 (16KB each)
#define SMEM_BYTES (3 * STAGE_BYTES + 1024)    // + alignment slack

static const int Mdim = 16384;
static const int Ddim = 1024;
static const int Fdim = 4096;
static const int Tdim = 2048;

// -------------------- scratch --------------------------------------------
__device__ float g_y  [16384 * 1024];
__device__ float g_Aa [16384 * 1024];
__device__ float g_Bb [16384 * 1024];
__device__ float g_sp [16384 * 1024];
__device__ float g_x1 [16384 * 1024];
__device__ float g_act[16384 * 4096];
__device__ float g_wr [16 * 1024 * 1024];      // tf32-rounded weights

// -------------------- helpers --------------------------------------------
__device__ __forceinline__ float rtf32(float v) {
    uint32_t r; asm("cvt.rna.tf32.f32 %0, %1;" : "=r"(r) : "f"(v));
    return __uint_as_float(r);
}
__device__ __forceinline__ float softplusf(float v) {
    return fmaxf(v, 0.f) + log1pf(expf(-fabsf(v)));
}
__device__ __forceinline__ float sigmoidf(float v) {
    return 1.f / (1.f + expf(-v));
}
__device__ __forceinline__ uint32_t smem_u32(const void* p) {
    uint32_t a;
    asm("{ .reg .u64 t; cvta.to.shared.u64 t, %1; cvt.u32.u64 %0, t; }"
        : "=r"(a) : "l"(p));
    return a;
}
#define SWZ(off) ((off) ^ (((off) >> 3) & 0x70))

__device__ __forceinline__ void cp16(uint32_t dst, const void* src) {
    asm volatile("cp.async.cg.shared.global [%0], [%1], 16;" :: "r"(dst), "l"(src));
}
__device__ __forceinline__ void cp_commit() {
    asm volatile("cp.async.commit_group;" ::: "memory");
}
template <int N>
__device__ __forceinline__ void cp_wait() {
    asm volatile("cp.async.wait_group %0;" :: "n"(N) : "memory");
}
__device__ __forceinline__ void ldsm4(uint32_t* r, uint32_t addr) {
    asm volatile("ldmatrix.sync.aligned.m8n8.x4.shared.b16 {%0,%1,%2,%3}, [%4];"
        : "=r"(r[0]), "=r"(r[1]), "=r"(r[2]), "=r"(r[3]) : "r"(addr));
}
__device__ __forceinline__ void mma8(float* d, const uint32_t* a, const uint32_t* b) {
    asm volatile(
        "mma.sync.aligned.m16n8k8.row.col.f32.tf32.tf32.f32 "
        "{%0,%1,%2,%3}, {%4,%5,%6,%7}, {%8,%9}, {%0,%1,%2,%3};"
        : "+f"(d[0]), "+f"(d[1]), "+f"(d[2]), "+f"(d[3])
        : "r"(a[0]), "r"(a[1]), "r"(a[2]), "r"(a[3]), "r"(b[0]), "r"(b[1]));
}

// -------------------- weight rounding --------------------------------------
__global__ void round_w_kernel(const float4* __restrict__ in,
                               float4* __restrict__ out) {
    int i = blockIdx.x * blockDim.x + threadIdx.x;
    float4 v = in[i];
    v.x = rtf32(v.x); v.y = rtf32(v.y); v.z = rtf32(v.z); v.w = rtf32(v.w);
    out[i] = v;
}

// -------------------- RMSNorm (tf32-rounded output) -------------------------
__global__ void rmsnorm_kernel(const float* __restrict__ x,
                               const float* __restrict__ w,
                               float* __restrict__ y) {
    const int row = blockIdx.x;
    const int t = threadIdx.x;
    float4 v = ((const float4*)(x + (size_t)row * 1024))[t];
    float ss = v.x * v.x + v.y * v.y + v.z * v.z + v.w * v.w;
    #pragma unroll
    for (int off = 16; off > 0; off >>= 1)
        ss += __shfl_xor_sync(0xffffffffu, ss, off);
    __shared__ float red[8];
    if ((t & 31) == 0) red[t >> 5] = ss;
    __syncthreads();
    float tot = red[0]+red[1]+red[2]+red[3]+red[4]+red[5]+red[6]+red[7];
    float rstd = rsqrtf(tot * (1.f / 1024.f) + 1e-6f);
    float4 wv = ((const float4*)w)[t];
    float4 o;
    o.x = rtf32(v.x * rstd * wv.x); o.y = rtf32(v.y * rstd * wv.y);
    o.z = rtf32(v.z * rstd * wv.z); o.w = rtf32(v.w * rstd * wv.w);
    ((float4*)(y + (size_t)row * 1024))[t] = o;
}

// -------------------- liquid + PLIF scan ------------------------------------
__global__ void scan_kernel(const float* __restrict__ Ab,
                            const float* __restrict__ Bb,
                            const float* __restrict__ log_tau,
                            const float* __restrict__ thr,
                            float* __restrict__ spike_in) {
    const int gid = blockIdx.x * blockDim.x + threadIdx.x;  // 0..8191
    const int d = gid & (Ddim - 1);
    const int b = gid >> 10;
    const float pdec = expf(-expf(-log_tau[d]));
    const float omp  = 1.f - pdec;
    const float th   = thr[d];
    size_t idx = (size_t)b * Tdim * Ddim + d;
    float h = 0.f, v = 0.f;
    for (int t = 0; t < Tdim; ++t, idx += Ddim) {
        float a  = Ab[idx];
        float bb = Bb[idx];
        h = tanhf(fmaf(a, h, bb));
        float vpre = fmaf(pdec, v, omp * h);
        float s = (vpre > th) ? 1.f : 0.f;
        v = vpre - s * th;
        spike_in[idx] = rtf32(s + h);
    }
}

// -------------------- mma.sync TF32 fused dual-GEMM --------------------------
// out[m,n] = sum_k A[m,k]*W{1,2}[n,k]; CTA = 128x128, warp tile 32x32 (dual).
// EPI 0: out1=exp(-softplus(c1+b1)*exp(Alog[n])), out2=softplus(c1+b1)*(c2+b2)
// EPI 1: out1 = extra + (c1+b1)*sigmoid(c2+b2)
// EPI 2: out1 = rtf32(silu(c1)*c2)
// EPI 3: out1 = extra + c1      (non-dual)
template <bool DUAL, int EPI>
__global__ void __launch_bounds__(NTHREADS, 1)
gemm_mma(const float* __restrict__ A,
         const float* __restrict__ W1,
         const float* __restrict__ W2,
         float* __restrict__ out1,
         float* __restrict__ out2,
         const float* __restrict__ bias1,
         const float* __restrict__ bias2,
         const float* __restrict__ extra,
         int K, int N) {
    extern __shared__ char smem[];
    const uint32_t stg0 = (smem_u32(smem) + 1023u) & ~1023u;

    const int tid  = threadIdx.x;
    const int warp = tid >> 5;
    const int lane = tid & 31;
    const int wm = warp >> 2;          // 0..3 (rows of 32)
    const int wn = warp & 3;           // 0..3 (cols of 32)
    const int bm = blockIdx.y * 128;
    const int bn = blockIdx.x * 128;

    const float* Arow = A  + (size_t)bm * K;
    const float* B1   = W1 + (size_t)bn * K;
    const float* B2   = DUAL ? (W2 + (size_t)bn * K) : W1;

    // loader: 16B chunks, 128B rows of BK=32 floats, SW128 swizzled
    const int NCHUNK = DUAL ? 3072 : 2048;
    auto load_stage = [&](int s, int kt) {
        const uint32_t sb = stg0 + s * STAGE_BYTES;
        const int ko = kt * 32;
        #pragma unroll
        for (int i = 0; i < 6; ++i) {
            const int c = tid + i * NTHREADS;
            if (c >= NCHUNK) break;
            const int mat = c >> 10;
            const int idx = c & 1023;
            const int row = idx >> 3;
            const int off = idx & 7;
            const float* src = (mat == 0) ? (Arow + (size_t)row * K + ko + off * 4)
                             : (mat == 1) ? (B1   + (size_t)row * K + ko + off * 4)
                                          : (B2   + (size_t)row * K + ko + off * 4);
            cp16(sb + mat * STAGE_A + SWZ(row * 128 + off * 16), src);
        }
        cp_commit();
    };

    float acc1[2][4][4];
    float acc2[2][4][4];
    #pragma unroll
    for (int i = 0; i < 2; ++i)
        #pragma unroll
        for (int j = 0; j < 4; ++j)
            #pragma unroll
            for (int k = 0; k < 4; ++k) { acc1[i][j][k] = 0.f; acc2[i][j][k] = 0.f; }

    const int NK = K / 32;
    load_stage(0, 0);
    load_stage(1, 1);
    load_stage(2, 2);

    // per-lane ldmatrix offsets (within a stage)
    const int mi     = lane >> 3;          // matrix index 0..3
    const int rin    = lane & 7;
    const int a_mrow = wm * 32 + (mi & 1) * 8 + rin;   // + mb*16
    const int a_koff = (mi >> 1) * 16;                  // + ks*32
    const int b_nrow = wn * 32 + (mi >> 1) * 8 + rin;   // + nbp*16
    const int b_koff = (mi & 1) * 16;                   // + ks*32

    for (int kt = 0; kt < NK; ++kt) {
        const int s = kt % 3;
        const int rem = NK - 1 - kt;
        if (rem >= 2)      cp_wait<2>();
        else if (rem == 1) cp_wait<1>();
        else               cp_wait<0>();
        __syncthreads();

        const uint32_t sA  = stg0 + s * STAGE_BYTES;
        const uint32_t sB1 = sA + STAGE_A;
        const uint32_t sB2 = sA + 2 * STAGE_A;

        #pragma unroll
        for (int ks = 0; ks < 4; ++ks) {
            uint32_t a[2][4];
            #pragma unroll
            for (int mb = 0; mb < 2; ++mb)
                ldsm4(a[mb], sA + SWZ((a_mrow + mb * 16) * 128 + ks * 32 + a_koff));

            uint32_t bf1[4][2], bf2[4][2];
            #pragma unroll
            for (int nbp = 0; nbp < 2; ++nbp) {
                uint32_t t[4];
                ldsm4(t, sB1 + SWZ((b_nrow + nbp * 16) * 128 + ks * 32 + b_koff));
                bf1[2*nbp][0] = t[0]; bf1[2*nbp][1] = t[1];
                bf1[2*nbp+1][0] = t[2]; bf1[2*nbp+1][1] = t[3];
                if (DUAL) {
                    ldsm4(t, sB2 + SWZ((b_nrow + nbp * 16) * 128 + ks * 32 + b_koff));
                    bf2[2*nbp][0] = t[0]; bf2[2*nbp][1] = t[1];
                    bf2[2*nbp+1][0] = t[2]; bf2[2*nbp+1][1] = t[3];
                }
            }

            #pragma unroll
            for (int mb = 0; mb < 2; ++mb)
                #pragma unroll
                for (int nb = 0; nb < 4; ++nb) {
                    mma8(acc1[mb][nb], a[mb], bf1[nb]);
                    if (DUAL) mma8(acc2[mb][nb], a[mb], bf2[nb]);
                }
        }
        __syncthreads();
        if (kt + 3 < NK) load_stage(s, kt + 3);
    }

    // ------------------------------- epilogue -------------------------------
    const int r_base = bm + wm * 32 + (lane >> 2);
    const int c_base = bn + wn * 32 + (lane & 3) * 2;

    #pragma unroll
    for (int mb = 0; mb < 2; ++mb) {
        #pragma unroll
        for (int nb = 0; nb < 4; ++nb) {
            const int r0 = r_base + mb * 16;
            const int r1 = r0 + 8;
            const int cc = c_base + nb * 8;
            const size_t o0 = (size_t)r0 * N + cc;
            const size_t o1 = (size_t)r1 * N + cc;
            const float* d1 = acc1[mb][nb];
            const float* d2 = acc2[mb][nb];
            float v00, v01, v10, v11;

            if (EPI == 0) {
                float b1a = __ldg(bias1 + cc), b1b = __ldg(bias1 + cc + 1);
                float b2a = __ldg(bias2 + cc), b2b = __ldg(bias2 + cc + 1);
                float ea  = expf(__ldg(extra + cc));
                float eb  = expf(__ldg(extra + cc + 1));
                float dl;
                dl = softplusf(d1[0] + b1a); v00 = expf(-dl * ea);
                float w00 = dl * (d2[0] + b2a);
                dl = softplusf(d1[1] + b1b); v01 = expf(-dl * eb);
                float w01 = dl * (d2[1] + b2b);
                dl = softplusf(d1[2] + b1a); v10 = expf(-dl * ea);
                float w10 = dl * (d2[2] + b2a);
                dl = softplusf(d1[3] + b1b); v11 = expf(-dl * eb);
                float w11 = dl * (d2[3] + b2b);
                *(float2*)(out1 + o0) = make_float2(v00, v01);
                *(float2*)(out1 + o1) = make_float2(v10, v11);
                *(float2*)(out2 + o0) = make_float2(w00, w01);
                *(float2*)(out2 + o1) = make_float2(w10, w11);
            } else if (EPI == 1) {
                float b1a = __ldg(bias1 + cc), b1b = __ldg(bias1 + cc + 1);
                float b2a = __ldg(bias2 + cc), b2b = __ldg(bias2 + cc + 1);
                float2 xa = *(const float2*)(extra + o0);
                float2 xb = *(const float2*)(extra + o1);
                v00 = xa.x + (d1[0] + b1a) * sigmoidf(d2[0] + b2a);
                v01 = xa.y + (d1[1] + b1b) * sigmoidf(d2[1] + b2b);
                v10 = xb.x + (d1[2] + b1a) * sigmoidf(d2[2] + b2a);
                v11 = xb.y + (d1[3] + b1b) * sigmoidf(d2[3] + b2b);
                *(float2*)(out1 + o0) = make_float2(v00, v01);
                *(float2*)(out1 + o1) = make_float2(v10, v11);
            } else if (EPI == 2) {
                v00 = rtf32(d1[0] * sigmoidf(d1[0]) * d2[0]);
                v01 = rtf32(d1[1] * sigmoidf(d1[1]) * d2[1]);
                v10 = rtf32(d1[2] * sigmoidf(d1[2]) * d2[2]);
                v11 = rtf32(d1[3] * sigmoidf(d1[3]) * d2[3]);
                *(float2*)(out1 + o0) = make_float2(v00, v01);
                *(float2*)(out1 + o1) = make_float2(v10, v11);
            } else {  // EPI == 3
                float2 xa = *(const float2*)(extra + o0);
                float2 xb = *(const float2*)(extra + o1);
                v00 = xa.x + d1[0]; v01 = xa.y + d1[1];
                v10 = xb.x + d1[2]; v11 = xb.y + d1[3];
                *(float2*)(out1 + o0) = make_float2(v00, v01);
                *(float2*)(out1 + o1) = make_float2(v10, v11);
            }
        }
    }
}

// ---------------------------------------------------------------------------
extern "C" void kernel_launch(void* const* d_in, const int* in_sizes, int n_in,
                              void* d_out, int out_size) {
    const float* x       = (const float*)d_in[0];
    const float* rms_w1  = (const float*)d_in[1];
    const float* rms_w2  = (const float*)d_in[2];
    const float* delta_w = (const float*)d_in[3];
    const float* delta_b = (const float*)d_in[4];
    const float* b_w     = (const float*)d_in[5];
    const float* b_b     = (const float*)d_in[6];
    const float* A_log   = (const float*)d_in[7];
    const float* log_tau = (const float*)d_in[8];
    const float* plif_thr= (const float*)d_in[9];
    const float* syn_w   = (const float*)d_in[10];
    const float* syn_b   = (const float*)d_in[11];
    const float* gate_w  = (const float*)d_in[12];
    const float* gate_b  = (const float*)d_in[13];
    const float* ffn_g_w = (const float*)d_in[14];
    const float* ffn_u_w = (const float*)d_in[15];
    const float* ffn_d_w = (const float*)d_in[16];
    float* out = (float*)d_out;

    float *y, *Aa, *Bb, *sp, *x1, *act, *wr;
    cudaGetSymbolAddress((void**)&y,   g_y);
    cudaGetSymbolAddress((void**)&Aa,  g_Aa);
    cudaGetSymbolAddress((void**)&Bb,  g_Bb);
    cudaGetSymbolAddress((void**)&sp,  g_sp);
    cudaGetSymbolAddress((void**)&x1,  g_x1);
    cudaGetSymbolAddress((void**)&act, g_act);
    cudaGetSymbolAddress((void**)&wr,  g_wr);

    cudaFuncSetAttribute(gemm_mma<true, 0>, cudaFuncAttributeMaxDynamicSharedMemorySize, SMEM_BYTES);
    cudaFuncSetAttribute(gemm_mma<true, 1>, cudaFuncAttributeMaxDynamicSharedMemorySize, SMEM_BYTES);
    cudaFuncSetAttribute(gemm_mma<true, 2>, cudaFuncAttributeMaxDynamicSharedMemorySize, SMEM_BYTES);
    cudaFuncSetAttribute(gemm_mma<false, 3>, cudaFuncAttributeMaxDynamicSharedMemorySize, SMEM_BYTES);

    const int M = Mdim, D = Ddim, F = Fdim;
    const int MEG = 1024 * 1024;

    float* wr_dw   = wr + 0 * MEG;
    float* wr_bw   = wr + 1 * MEG;
    float* wr_syn  = wr + 2 * MEG;
    float* wr_gate = wr + 3 * MEG;
    float* wr_g    = wr + 4 * MEG;
    float* wr_u    = wr + 8 * MEG;
    float* wr_d    = wr + 12 * MEG;
    round_w_kernel<<<MEG / 1024, 256>>>((const float4*)delta_w, (float4*)wr_dw);
    round_w_kernel<<<MEG / 1024, 256>>>((const float4*)b_w,     (float4*)wr_bw);
    round_w_kernel<<<MEG / 1024, 256>>>((const float4*)syn_w,   (float4*)wr_syn);
    round_w_kernel<<<MEG / 1024, 256>>>((const float4*)gate_w,  (float4*)wr_gate);
    round_w_kernel<<<4 * MEG / 1024, 256>>>((const float4*)ffn_g_w, (float4*)wr_g);
    round_w_kernel<<<4 * MEG / 1024, 256>>>((const float4*)ffn_u_w, (float4*)wr_u);
    round_w_kernel<<<4 * MEG / 1024, 256>>>((const float4*)ffn_d_w, (float4*)wr_d);

    // 1) y1 = rmsnorm(x)
    rmsnorm_kernel<<<M, 256>>>(x, rms_w1, y);

    // 2) A, bvec (dual GEMM, fused softplus/exp epilogue)
    dim3 g1(D / 128, M / 128);
    gemm_mma<true, 0><<<g1, NTHREADS, SMEM_BYTES>>>(y, wr_dw, wr_bw, Aa, Bb,
                                                    delta_b, b_b, A_log, D, D);
    // 3) scan -> spike_in
    scan_kernel<<<64, 128>>>(Aa, Bb, log_tau, plif_thr, sp);

    // 4) x1 = x + syn*sigmoid(gate)
    gemm_mma<true, 1><<<g1, NTHREADS, SMEM_BYTES>>>(sp, wr_syn, wr_gate, x1, nullptr,
                                                    syn_b, gate_b, x, D, D);
    // 5) y2 = rmsnorm(x1)
    rmsnorm_kernel<<<M, 256>>>(x1, rms_w2, y);

    // 6) act = silu(y2@g^T)*(y2@u^T)
    dim3 g3(F / 128, M / 128);
    gemm_mma<true, 2><<<g3, NTHREADS, SMEM_BYTES>>>(y, wr_g, wr_u, act, nullptr,
                                                    nullptr, nullptr, nullptr, D, F);
    // 7) out = x1 + act@d^T
    dim3 g4(D / 128, M / 128);
    gemm_mma<false, 3><<<g4, NTHREADS, SMEM_BYTES>>>(act, wr_d, nullptr, out, nullptr,
                                                     nullptr, nullptr, x1, F, D);
}

// round 4
// speedup vs baseline: 4.5480x; 1.2904x over previous
#include <cuda_runtime.h>
#include <cuda_bf16.h>
#include <math.h>
#include <stdint.h>

// ---------------------------------------------------------------------------
// FusedHybridBlock via mma.sync (tcgen05 unavailable at compute_103 virtual
// arch). TF32 m16n8k8 for GEMMs feeding the spike threshold / residual trunk;
// BF16 m16n8k16 (2x rate) for the FFN gate/up GEMM whose error is diluted by
// the residual. 4-stage cp.async pipeline with ONE barrier per k-tile.
// ---------------------------------------------------------------------------

#define NTHREADS   512
#define STAGE_A    16384
#define STAGE_BYTES 49152                       // A + B1 + B2 (16KB each)
#define NSTG       4
#define SMEM_BYTES (NSTG * STAGE_BYTES + 1024)  // 197632

static const int Mdim = 16384;
static const int Ddim = 1024;
static const int Fdim = 4096;
static const int Tdim = 2048;

// -------------------- scratch ----------------------------------------------
__device__ float g_y  [16384 * 1024];          // y1 (tf32-rounded fp32)
__device__ float g_Aa [16384 * 1024];
__device__ float g_Bb [16384 * 1024];
__device__ float g_sp [16384 * 1024];
__device__ float g_x1 [16384 * 1024];
__device__ float g_act[16384 * 4096];
__device__ float g_wr [8 * 1024 * 1024];       // tf32-rounded weights
__device__ __nv_bfloat16 g_y2 [16384 * 1024];  // y2 in bf16
__device__ __nv_bfloat16 g_wbg[4 * 1024 * 1024];
__device__ __nv_bfloat16 g_wbu[4 * 1024 * 1024];

// -------------------- helpers ----------------------------------------------
__device__ __forceinline__ float rtf32(float v) {
    uint32_t r; asm("cvt.rna.tf32.f32 %0, %1;" : "=r"(r) : "f"(v));
    return __uint_as_float(r);
}
__device__ __forceinline__ float softplusf(float v) {
    return fmaxf(v, 0.f) + log1pf(expf(-fabsf(v)));
}
__device__ __forceinline__ float sigmoidf(float v) {
    return 1.f / (1.f + expf(-v));
}
__device__ __forceinline__ uint32_t smem_u32(const void* p) {
    uint32_t a;
    asm("{ .reg .u64 t; cvta.to.shared.u64 t, %1; cvt.u32.u64 %0, t; }"
        : "=r"(a) : "l"(p));
    return a;
}
#define SWZ(off) ((off) ^ (((off) >> 3) & 0x70))

__device__ __forceinline__ void cp16(uint32_t dst, const void* src) {
    asm volatile("cp.async.cg.shared.global [%0], [%1], 16;" :: "r"(dst), "l"(src));
}
__device__ __forceinline__ void cp_commit() {
    asm volatile("cp.async.commit_group;" ::: "memory");
}
template <int N>
__device__ __forceinline__ void cp_wait() {
    asm volatile("cp.async.wait_group %0;" :: "n"(N) : "memory");
}
__device__ __forceinline__ void ldsm4(uint32_t* r, uint32_t addr) {
    asm volatile("ldmatrix.sync.aligned.m8n8.x4.shared.b16 {%0,%1,%2,%3}, [%4];"
        : "=r"(r[0]), "=r"(r[1]), "=r"(r[2]), "=r"(r[3]) : "r"(addr));
}
__device__ __forceinline__ void mma8(float* d, const uint32_t* a, const uint32_t* b) {
    asm volatile(
        "mma.sync.aligned.m16n8k8.row.col.f32.tf32.tf32.f32 "
        "{%0,%1,%2,%3}, {%4,%5,%6,%7}, {%8,%9}, {%0,%1,%2,%3};"
        : "+f"(d[0]), "+f"(d[1]), "+f"(d[2]), "+f"(d[3])
        : "r"(a[0]), "r"(a[1]), "r"(a[2]), "r"(a[3]), "r"(b[0]), "r"(b[1]));
}
__device__ __forceinline__ void mma16bf(float* d, const uint32_t* a, const uint32_t* b) {
    asm volatile(
        "mma.sync.aligned.m16n8k16.row.col.f32.bf16.bf16.f32 "
        "{%0,%1,%2,%3}, {%4,%5,%6,%7}, {%8,%9}, {%0,%1,%2,%3};"
        : "+f"(d[0]), "+f"(d[1]), "+f"(d[2]), "+f"(d[3])
        : "r"(a[0]), "r"(a[1]), "r"(a[2]), "r"(a[3]), "r"(b[0]), "r"(b[1]));
}

// -------------------- weight conversion -------------------------------------
__global__ void round_w_kernel(const float4* __restrict__ in,
                               float4* __restrict__ out) {
    int i = blockIdx.x * blockDim.x + threadIdx.x;
    float4 v = in[i];
    v.x = rtf32(v.x); v.y = rtf32(v.y); v.z = rtf32(v.z); v.w = rtf32(v.w);
    out[i] = v;
}
__global__ void tobf16_kernel(const float4* __restrict__ in,
                              __nv_bfloat162* __restrict__ out) {
    int i = blockIdx.x * blockDim.x + threadIdx.x;
    float4 v = in[i];
    out[2 * i]     = __floats2bfloat162_rn(v.x, v.y);
    out[2 * i + 1] = __floats2bfloat162_rn(v.z, v.w);
}

// -------------------- RMSNorm variants ---------------------------------------
template <bool BF16OUT>
__global__ void rmsnorm_kernel(const float* __restrict__ x,
                               const float* __restrict__ w,
                               float* __restrict__ yf,
                               __nv_bfloat16* __restrict__ yb) {
    const int row = blockIdx.x;
    const int t = threadIdx.x;
    float4 v = ((const float4*)(x + (size_t)row * 1024))[t];
    float ss = v.x * v.x + v.y * v.y + v.z * v.z + v.w * v.w;
    #pragma unroll
    for (int off = 16; off > 0; off >>= 1)
        ss += __shfl_xor_sync(0xffffffffu, ss, off);
    __shared__ float red[8];
    if ((t & 31) == 0) red[t >> 5] = ss;
    __syncthreads();
    float tot = red[0]+red[1]+red[2]+red[3]+red[4]+red[5]+red[6]+red[7];
    float rstd = rsqrtf(tot * (1.f / 1024.f) + 1e-6f);
    float4 wv = ((const float4*)w)[t];
    float a = v.x * rstd * wv.x, b = v.y * rstd * wv.y;
    float c = v.z * rstd * wv.z, d = v.w * rstd * wv.w;
    if (BF16OUT) {
        __nv_bfloat162* o = (__nv_bfloat162*)(yb + (size_t)row * 1024);
        o[2 * t]     = __floats2bfloat162_rn(a, b);
        o[2 * t + 1] = __floats2bfloat162_rn(c, d);
    } else {
        ((float4*)(yf + (size_t)row * 1024))[t] =
            make_float4(rtf32(a), rtf32(b), rtf32(c), rtf32(d));
    }
}

// -------------------- liquid + PLIF scan -------------------------------------
__global__ void scan_kernel(const float* __restrict__ Ab,
                            const float* __restrict__ Bb,
                            const float* __restrict__ log_tau,
                            const float* __restrict__ thr,
                            float* __restrict__ spike_in) {
    const int gid = blockIdx.x * blockDim.x + threadIdx.x;  // 0..8191
    const int d = gid & (Ddim - 1);
    const int b = gid >> 10;
    const float pdec = expf(-expf(-log_tau[d]));
    const float omp  = 1.f - pdec;
    const float th   = thr[d];
    size_t idx = (size_t)b * Tdim * Ddim + d;
    float h = 0.f, v = 0.f;
    #pragma unroll 4
    for (int t = 0; t < Tdim; ++t, idx += Ddim) {
        float a  = Ab[idx];
        float bb = Bb[idx];
        h = tanhf(fmaf(a, h, bb));
        float vpre = fmaf(pdec, v, omp * h);
        float s = (vpre > th) ? 1.f : 0.f;
        v = vpre - s * th;
        spike_in[idx] = rtf32(s + h);
    }
}

// ==================== TF32 fused dual-GEMM (EPI 0/1/3) ========================
// out[m,n] = sum_k A[m,k]*W{1,2}[n,k]; CTA 128x128; warp tile 32x32 (dual).
template <bool DUAL, int EPI>
__global__ void __launch_bounds__(NTHREADS, 1)
gemm_mma(const float* __restrict__ A,
         const float* __restrict__ W1,
         const float* __restrict__ W2,
         float* __restrict__ out1,
         float* __restrict__ out2,
         const float* __restrict__ bias1,
         const float* __restrict__ bias2,
         const float* __restrict__ extra,
         int K, int N) {
    extern __shared__ char smem[];
    const uint32_t stg0 = (smem_u32(smem) + 1023u) & ~1023u;

    const int tid  = threadIdx.x;
    const int warp = tid >> 5;
    const int lane = tid & 31;
    const int wm = warp >> 2;
    const int wn = warp & 3;
    const int bm = blockIdx.y * 128;
    const int bn = blockIdx.x * 128;

    const float* Arow = A  + (size_t)bm * K;
    const float* B1   = W1 + (size_t)bn * K;
    const float* B2   = DUAL ? (W2 + (size_t)bn * K) : W1;

    const int NCHUNK = DUAL ? 3072 : 2048;
    auto load_stage = [&](int s, int kt) {
        const uint32_t sb = stg0 + s * STAGE_BYTES;
        const int ko = kt * 32;
        #pragma unroll
        for (int i = 0; i < 6; ++i) {
            const int c = tid + i * NTHREADS;
            if (c >= NCHUNK) break;
            const int mat = c >> 10;
            const int idx = c & 1023;
            const int row = idx >> 3;
            const int off = idx & 7;
            const float* src = (mat == 0) ? (Arow + (size_t)row * K + ko + off * 4)
                             : (mat == 1) ? (B1   + (size_t)row * K + ko + off * 4)
                                          : (B2   + (size_t)row * K + ko + off * 4);
            cp16(sb + mat * STAGE_A + SWZ(row * 128 + off * 16), src);
        }
        cp_commit();
    };

    float acc1[2][4][4];
    float acc2[2][4][4];
    #pragma unroll
    for (int i = 0; i < 2; ++i)
        #pragma unroll
        for (int j = 0; j < 4; ++j)
            #pragma unroll
            for (int k = 0; k < 4; ++k) { acc1[i][j][k] = 0.f; acc2[i][j][k] = 0.f; }

    const int NK = K / 32;
    load_stage(0, 0);
    load_stage(1, 1);
    load_stage(2, 2);

    const int mi     = lane >> 3;
    const int rin    = lane & 7;
    const int a_mrow = wm * 32 + (mi & 1) * 8 + rin;
    const int a_koff = (mi >> 1) * 16;
    const int b_nrow = wn * 32 + (mi >> 1) * 8 + rin;
    const int b_koff = (mi & 1) * 16;

    for (int kt = 0; kt < NK; ++kt) {
        const int s = kt % NSTG;
        const int rem = NK - 1 - kt;
        if (rem >= 2)      cp_wait<2>();
        else if (rem == 1) cp_wait<1>();
        else               cp_wait<0>();
        __syncthreads();

        const uint32_t sA  = stg0 + s * STAGE_BYTES;
        const uint32_t sB1 = sA + STAGE_A;
        const uint32_t sB2 = sA + 2 * STAGE_A;

        #pragma unroll
        for (int ks = 0; ks < 4; ++ks) {
            uint32_t a[2][4];
            #pragma unroll
            for (int mb = 0; mb < 2; ++mb)
                ldsm4(a[mb], sA + SWZ((a_mrow + mb * 16) * 128 + ks * 32 + a_koff));

            uint32_t bf1[4][2], bf2[4][2];
            #pragma unroll
            for (int nbp = 0; nbp < 2; ++nbp) {
                uint32_t t[4];
                ldsm4(t, sB1 + SWZ((b_nrow + nbp * 16) * 128 + ks * 32 + b_koff));
                bf1[2*nbp][0] = t[0]; bf1[2*nbp][1] = t[1];
                bf1[2*nbp+1][0] = t[2]; bf1[2*nbp+1][1] = t[3];
                if (DUAL) {
                    ldsm4(t, sB2 + SWZ((b_nrow + nbp * 16) * 128 + ks * 32 + b_koff));
                    bf2[2*nbp][0] = t[0]; bf2[2*nbp][1] = t[1];
                    bf2[2*nbp+1][0] = t[2]; bf2[2*nbp+1][1] = t[3];
                }
            }

            #pragma unroll
            for (int mb = 0; mb < 2; ++mb)
                #pragma unroll
                for (int nb = 0; nb < 4; ++nb) {
                    mma8(acc1[mb][nb], a[mb], bf1[nb]);
                    if (DUAL) mma8(acc2[mb][nb], a[mb], bf2[nb]);
                }
        }
        // 4 buffers, 3 in flight: the buffer written below was last READ at
        // iteration kt-1, ordered by the barrier above -> no second barrier.
        if (kt + 3 < NK) load_stage((kt + 3) % NSTG, kt + 3);
    }

    // ------------------------------- epilogue -------------------------------
    const int r_base = bm + wm * 32 + (lane >> 2);
    const int c_base = bn + wn * 32 + (lane & 3) * 2;

    #pragma unroll
    for (int mb = 0; mb < 2; ++mb) {
        #pragma unroll
        for (int nb = 0; nb < 4; ++nb) {
            const int r0 = r_base + mb * 16;
            const int r1 = r0 + 8;
            const int cc = c_base + nb * 8;
            const size_t o0 = (size_t)r0 * N + cc;
            const size_t o1 = (size_t)r1 * N + cc;
            const float* d1 = acc1[mb][nb];
            const float* d2 = acc2[mb][nb];
            float v00, v01, v10, v11;

            if (EPI == 0) {
                float b1a = __ldg(bias1 + cc), b1b = __ldg(bias1 + cc + 1);
                float b2a = __ldg(bias2 + cc), b2b = __ldg(bias2 + cc + 1);
                float ea  = expf(__ldg(extra + cc));
                float eb  = expf(__ldg(extra + cc + 1));
                float dl;
                dl = softplusf(d1[0] + b1a); v00 = expf(-dl * ea);
                float w00 = dl * (d2[0] + b2a);
                dl = softplusf(d1[1] + b1b); v01 = expf(-dl * eb);
                float w01 = dl * (d2[1] + b2b);
                dl = softplusf(d1[2] + b1a); v10 = expf(-dl * ea);
                float w10 = dl * (d2[2] + b2a);
                dl = softplusf(d1[3] + b1b); v11 = expf(-dl * eb);
                float w11 = dl * (d2[3] + b2b);
                *(float2*)(out1 + o0) = make_float2(v00, v01);
                *(float2*)(out1 + o1) = make_float2(v10, v11);
                *(float2*)(out2 + o0) = make_float2(w00, w01);
                *(float2*)(out2 + o1) = make_float2(w10, w11);
            } else if (EPI == 1) {
                float b1a = __ldg(bias1 + cc), b1b = __ldg(bias1 + cc + 1);
                float b2a = __ldg(bias2 + cc), b2b = __ldg(bias2 + cc + 1);
                float2 xa = *(const float2*)(extra + o0);
                float2 xb = *(const float2*)(extra + o1);
                v00 = xa.x + (d1[0] + b1a) * sigmoidf(d2[0] + b2a);
                v01 = xa.y + (d1[1] + b1b) * sigmoidf(d2[1] + b2b);
                v10 = xb.x + (d1[2] + b1a) * sigmoidf(d2[2] + b2a);
                v11 = xb.y + (d1[3] + b1b) * sigmoidf(d2[3] + b2b);
                *(float2*)(out1 + o0) = make_float2(v00, v01);
                *(float2*)(out1 + o1) = make_float2(v10, v11);
            } else {  // EPI == 3
                float2 xa = *(const float2*)(extra + o0);
                float2 xb = *(const float2*)(extra + o1);
                v00 = xa.x + d1[0]; v01 = xa.y + d1[1];
                v10 = xb.x + d1[2]; v11 = xb.y + d1[3];
                *(float2*)(out1 + o0) = make_float2(v00, v01);
                *(float2*)(out1 + o1) = make_float2(v10, v11);
            }
        }
    }
}

// ==================== BF16 fused dual-GEMM (FFN gate/up) ======================
// out = rtf32(silu(A@W1^T) * (A@W2^T)); A,W in bf16; BK=64 elements (128B rows)
__global__ void __launch_bounds__(NTHREADS, 1)
gemm_bf16_ffn(const __nv_bfloat16* __restrict__ A,
              const __nv_bfloat16* __restrict__ W1,
              const __nv_bfloat16* __restrict__ W2,
              float* __restrict__ out1,
              int K, int N) {
    extern __shared__ char smem[];
    const uint32_t stg0 = (smem_u32(smem) + 1023u) & ~1023u;

    const int tid  = threadIdx.x;
    const int warp = tid >> 5;
    const int lane = tid & 31;
    const int wm = warp >> 2;
    const int wn = warp & 3;
    const int bm = blockIdx.y * 128;
    const int bn = blockIdx.x * 128;

    const char* Arow = (const char*)(A  + (size_t)bm * K);
    const char* B1   = (const char*)(W1 + (size_t)bn * K);
    const char* B2   = (const char*)(W2 + (size_t)bn * K);
    const size_t rs = (size_t)K * 2;           // row stride bytes

    auto load_stage = [&](int s, int kt) {
        const uint32_t sb = stg0 + s * STAGE_BYTES;
        const size_t ko = (size_t)kt * 128;    // bytes
        #pragma unroll
        for (int i = 0; i < 6; ++i) {
            const int c = tid + i * NTHREADS;
            const int mat = c >> 10;
            const int idx = c & 1023;
            const int row = idx >> 3;
            const int off = idx & 7;
            const char* src = (mat == 0) ? (Arow + row * rs + ko + off * 16)
                            : (mat == 1) ? (B1   + row * rs + ko + off * 16)
                                         : (B2   + row * rs + ko + off * 16);
            cp16(sb + mat * STAGE_A + SWZ(row * 128 + off * 16), src);
        }
        cp_commit();
    };

    float acc1[2][4][4];
    float acc2[2][4][4];
    #pragma unroll
    for (int i = 0; i < 2; ++i)
        #pragma unroll
        for (int j = 0; j < 4; ++j)
            #pragma unroll
            for (int k = 0; k < 4; ++k) { acc1[i][j][k] = 0.f; acc2[i][j][k] = 0.f; }

    const int NK = K / 64;                     // 16
    load_stage(0, 0);
    load_stage(1, 1);
    load_stage(2, 2);

    const int mi  = lane >> 3;
    const int rin = lane & 7;
    // A 16x16 frag: mi0:(m+0,kb0) mi1:(m+8,kb0) mi2:(m+0,kb1) mi3:(m+8,kb1)
    const int a_mrow = wm * 32 + (mi & 1) * 8 + rin;
    const int a_koff = (mi >> 1) * 16;         // bytes (8 bf16)
    // B x4 covers 2 n-octs x 2 k-blocks: mi0:(n0,kb0) mi1:(n0,kb1) mi2:(n8,kb0) mi3:(n8,kb1)
    const int b_nrow = wn * 32 + (mi >> 1) * 8 + rin;
    const int b_koff = (mi & 1) * 16;

    for (int kt = 0; kt < NK; ++kt) {
        const int s = kt % NSTG;
        const int rem = NK - 1 - kt;
        if (rem >= 2)      cp_wait<2>();
        else if (rem == 1) cp_wait<1>();
        else               cp_wait<0>();
        __syncthreads();

        const uint32_t sA  = stg0 + s * STAGE_BYTES;
        const uint32_t sB1 = sA + STAGE_A;
        const uint32_t sB2 = sA + 2 * STAGE_A;

        #pragma unroll
        for (int ks = 0; ks < 4; ++ks) {       // 4 x k16 chunks (32B each)
            uint32_t a[2][4];
            #pragma unroll
            for (int mb = 0; mb < 2; ++mb)
                ldsm4(a[mb], sA + SWZ((a_mrow + mb * 16) * 128 + ks * 32 + a_koff));

            uint32_t bf1[4][2], bf2[4][2];
            #pragma unroll
            for (int nbp = 0; nbp < 2; ++nbp) {
                uint32_t t[4];
                ldsm4(t, sB1 + SWZ((b_nrow + nbp * 16) * 128 + ks * 32 + b_koff));
                bf1[2*nbp][0] = t[0]; bf1[2*nbp][1] = t[1];
                bf1[2*nbp+1][0] = t[2]; bf1[2*nbp+1][1] = t[3];
                ldsm4(t, sB2 + SWZ((b_nrow + nbp * 16) * 128 + ks * 32 + b_koff));
                bf2[2*nbp][0] = t[0]; bf2[2*nbp][1] = t[1];
                bf2[2*nbp+1][0] = t[2]; bf2[2*nbp+1][1] = t[3];
            }

            #pragma unroll
            for (int mb = 0; mb < 2; ++mb)
                #pragma unroll
                for (int nb = 0; nb < 4; ++nb) {
                    mma16bf(acc1[mb][nb], a[mb], bf1[nb]);
                    mma16bf(acc2[mb][nb], a[mb], bf2[nb]);
                }
        }
        if (kt + 3 < NK) load_stage((kt + 3) % NSTG, kt + 3);
    }

    const int r_base = bm + wm * 32 + (lane >> 2);
    const int c_base = bn + wn * 32 + (lane & 3) * 2;
    #pragma unroll
    for (int mb = 0; mb < 2; ++mb)
        #pragma unroll
        for (int nb = 0; nb < 4; ++nb) {
            const int r0 = r_base + mb * 16;
            const int r1 = r0 + 8;
            const int cc = c_base + nb * 8;
            const size_t o0 = (size_t)r0 * N + cc;
            const size_t o1 = (size_t)r1 * N + cc;
            const float* d1 = acc1[mb][nb];
            const float* d2 = acc2[mb][nb];
            float v00 = rtf32(d1[0] * sigmoidf(d1[0]) * d2[0]);
            float v01 = rtf32(d1[1] * sigmoidf(d1[1]) * d2[1]);
            float v10 = rtf32(d1[2] * sigmoidf(d1[2]) * d2[2]);
            float v11 = rtf32(d1[3] * sigmoidf(d1[3]) * d2[3]);
            *(float2*)(out1 + o0) = make_float2(v00, v01);
            *(float2*)(out1 + o1) = make_float2(v10, v11);
        }
}

// ---------------------------------------------------------------------------
extern "C" void kernel_launch(void* const* d_in, const int* in_sizes, int n_in,
                              void* d_out, int out_size) {
    const float* x       = (const float*)d_in[0];
    const float* rms_w1  = (const float*)d_in[1];
    const float* rms_w2  = (const float*)d_in[2];
    const float* delta_w = (const float*)d_in[3];
    const float* delta_b = (const float*)d_in[4];
    const float* b_w     = (const float*)d_in[5];
    const float* b_b     = (const float*)d_in[6];
    const float* A_log   = (const float*)d_in[7];
    const float* log_tau = (const float*)d_in[8];
    const float* plif_thr= (const float*)d_in[9];
    const float* syn_w   = (const float*)d_in[10];
    const float* syn_b   = (const float*)d_in[11];
    const float* gate_w  = (const float*)d_in[12];
    const float* gate_b  = (const float*)d_in[13];
    const float* ffn_g_w = (const float*)d_in[14];
    const float* ffn_u_w = (const float*)d_in[15];
    const float* ffn_d_w = (const float*)d_in[16];
    float* out = (float*)d_out;

    float *y, *Aa, *Bb, *sp, *x1, *act, *wr;
    __nv_bfloat16 *y2, *wbg, *wbu;
    cudaGetSymbolAddress((void**)&y,   g_y);
    cudaGetSymbolAddress((void**)&Aa,  g_Aa);
    cudaGetSymbolAddress((void**)&Bb,  g_Bb);
    cudaGetSymbolAddress((void**)&sp,  g_sp);
    cudaGetSymbolAddress((void**)&x1,  g_x1);
    cudaGetSymbolAddress((void**)&act, g_act);
    cudaGetSymbolAddress((void**)&wr,  g_wr);
    cudaGetSymbolAddress((void**)&y2,  g_y2);
    cudaGetSymbolAddress((void**)&wbg, g_wbg);
    cudaGetSymbolAddress((void**)&wbu, g_wbu);

    cudaFuncSetAttribute(gemm_mma<true, 0>, cudaFuncAttributeMaxDynamicSharedMemorySize, SMEM_BYTES);
    cudaFuncSetAttribute(gemm_mma<true, 1>, cudaFuncAttributeMaxDynamicSharedMemorySize, SMEM_BYTES);
    cudaFuncSetAttribute(gemm_mma<false, 3>, cudaFuncAttributeMaxDynamicSharedMemorySize, SMEM_BYTES);
    cudaFuncSetAttribute(gemm_bf16_ffn, cudaFuncAttributeMaxDynamicSharedMemorySize, SMEM_BYTES);

    const int M = Mdim, D = Ddim, F = Fdim;
    const int MEG = 1024 * 1024;

    float* wr_dw   = wr + 0 * MEG;
    float* wr_bw   = wr + 1 * MEG;
    float* wr_syn  = wr + 2 * MEG;
    float* wr_gate = wr + 3 * MEG;
    float* wr_d    = wr + 4 * MEG;
    round_w_kernel<<<MEG / 1024, 256>>>((const float4*)delta_w, (float4*)wr_dw);
    round_w_kernel<<<MEG / 1024, 256>>>((const float4*)b_w,     (float4*)wr_bw);
    round_w_kernel<<<MEG / 1024, 256>>>((const float4*)syn_w,   (float4*)wr_syn);
    round_w_kernel<<<MEG / 1024, 256>>>((const float4*)gate_w,  (float4*)wr_gate);
    round_w_kernel<<<4 * MEG / 1024, 256>>>((const float4*)ffn_d_w, (float4*)wr_d);
    tobf16_kernel<<<4 * MEG / 1024, 256>>>((const float4*)ffn_g_w, (__nv_bfloat162*)wbg);
    tobf16_kernel<<<4 * MEG / 1024, 256>>>((const float4*)ffn_u_w, (__nv_bfloat162*)wbu);

    // 1) y1 = rmsnorm(x)  (tf32-rounded fp32)
    rmsnorm_kernel<false><<<M, 256>>>(x, rms_w1, y, nullptr);

    // 2) A, bvec (dual tf32 GEMM, fused softplus/exp epilogue)
    dim3 g1(D / 128, M / 128);
    gemm_mma<true, 0><<<g1, NTHREADS, SMEM_BYTES>>>(y, wr_dw, wr_bw, Aa, Bb,
                                                    delta_b, b_b, A_log, D, D);
    // 3) scan -> spike_in
    scan_kernel<<<64, 128>>>(Aa, Bb, log_tau, plif_thr, sp);

    // 4) x1 = x + syn*sigmoid(gate)  (dual tf32 GEMM)
    gemm_mma<true, 1><<<g1, NTHREADS, SMEM_BYTES>>>(sp, wr_syn, wr_gate, x1, nullptr,
                                                    syn_b, gate_b, x, D, D);
    // 5) y2 = rmsnorm(x1) in bf16
    rmsnorm_kernel<true><<<M, 256>>>(x1, rms_w2, nullptr, y2);

    // 6) act = silu(y2@g^T)*(y2@u^T)  (dual bf16 GEMM, 2x rate)
    dim3 g3(F / 128, M / 128);
    gemm_bf16_ffn<<<g3, NTHREADS, SMEM_BYTES>>>(y2, wbg, wbu, act, D, F);

    // 7) out = x1 + act@d^T  (tf32)
    dim3 g4(D / 128, M / 128);
    gemm_mma<false, 3><<<g4, NTHREADS, SMEM_BYTES>>>(act, wr_d, nullptr, out, nullptr,
                                                     nullptr, nullptr, x1, F, D);
}

// round 5
// speedup vs baseline: 6.1925x; 1.3616x over previous
#include <cuda_runtime.h>
#include <cuda_fp16.h>
#include <math.h>
#include <stdint.h>

// ---------------------------------------------------------------------------
// FusedHybridBlock, all GEMMs in fp16 mma.sync.m16n8k16 (f32 accumulate).
// fp16 has an 11-bit significand == tf32, at 2x the HMMA rate; all tensors
// here fit fp16 range, so this is error-neutral vs the tf32 path while
// halving GEMM time AND halving smem/gmem tile traffic.
//   RMSNorm -> dualGEMM(delta,b)+nonlin -> liquid+PLIF scan ->
//   dualGEMM(syn,gate)+residual -> RMSNorm -> dualGEMM(ffn g,u)+SiLU ->
//   GEMM(down)+residual
// CTA 128x128, 16 warps, warp tile 32x32 (dual-accumulate), BK=64 halves
// (128B rows, SW128), 4-stage cp.async pipeline, one barrier per k-tile.
// ---------------------------------------------------------------------------

#define NTHREADS   512
#define STAGE_A    16384
#define STAGE_BYTES 49152                       // A + B1 + B2 (16KB each)
#define NSTG       4
#define SMEM_BYTES (NSTG * STAGE_BYTES + 1024)  // 197632

static const int Mdim = 16384;
static const int Ddim = 1024;
static const int Fdim = 4096;
static const int Tdim = 2048;

// -------------------- scratch ----------------------------------------------
__device__ float  g_Aa [16384 * 1024];
__device__ float  g_Bb [16384 * 1024];
__device__ float  g_x1 [16384 * 1024];
__device__ __half g_y1 [16384 * 1024];
__device__ __half g_sp [16384 * 1024];
__device__ __half g_y2 [16384 * 1024];
__device__ __half g_act[16384 * 4096];
__device__ __half g_wh [16 * 1024 * 1024];     // all weights in fp16

// -------------------- helpers ----------------------------------------------
__device__ __forceinline__ float softplusf(float v) {
    return fmaxf(v, 0.f) + log1pf(expf(-fabsf(v)));
}
__device__ __forceinline__ float sigmoidf(float v) {
    return 1.f / (1.f + expf(-v));
}
__device__ __forceinline__ uint32_t smem_u32(const void* p) {
    uint32_t a;
    asm("{ .reg .u64 t; cvta.to.shared.u64 t, %1; cvt.u32.u64 %0, t; }"
        : "=r"(a) : "l"(p));
    return a;
}
#define SWZ(off) ((off) ^ (((off) >> 3) & 0x70))

__device__ __forceinline__ void cp16(uint32_t dst, const void* src) {
    asm volatile("cp.async.cg.shared.global [%0], [%1], 16;" :: "r"(dst), "l"(src));
}
__device__ __forceinline__ void cp_commit() {
    asm volatile("cp.async.commit_group;" ::: "memory");
}
template <int N>
__device__ __forceinline__ void cp_wait() {
    asm volatile("cp.async.wait_group %0;" :: "n"(N) : "memory");
}
__device__ __forceinline__ void ldsm4(uint32_t* r, uint32_t addr) {
    asm volatile("ldmatrix.sync.aligned.m8n8.x4.shared.b16 {%0,%1,%2,%3}, [%4];"
        : "=r"(r[0]), "=r"(r[1]), "=r"(r[2]), "=r"(r[3]) : "r"(addr));
}
__device__ __forceinline__ void mma16h(float* d, const uint32_t* a, const uint32_t* b) {
    asm volatile(
        "mma.sync.aligned.m16n8k16.row.col.f32.f16.f16.f32 "
        "{%0,%1,%2,%3}, {%4,%5,%6,%7}, {%8,%9}, {%0,%1,%2,%3};"
        : "+f"(d[0]), "+f"(d[1]), "+f"(d[2]), "+f"(d[3])
        : "r"(a[0]), "r"(a[1]), "r"(a[2]), "r"(a[3]), "r"(b[0]), "r"(b[1]));
}

// -------------------- weight conversion fp32 -> fp16 -------------------------
__global__ void w2h_kernel(const float4* __restrict__ in,
                           __half2* __restrict__ out) {
    int i = blockIdx.x * blockDim.x + threadIdx.x;
    float4 v = in[i];
    out[2 * i]     = __floats2half2_rn(v.x, v.y);
    out[2 * i + 1] = __floats2half2_rn(v.z, v.w);
}

// -------------------- RMSNorm -> fp16 ----------------------------------------
__global__ void rmsnorm_kernel(const float* __restrict__ x,
                               const float* __restrict__ w,
                               __half* __restrict__ y) {
    const int row = blockIdx.x;
    const int t = threadIdx.x;
    float4 v = ((const float4*)(x + (size_t)row * 1024))[t];
    float ss = v.x * v.x + v.y * v.y + v.z * v.z + v.w * v.w;
    #pragma unroll
    for (int off = 16; off > 0; off >>= 1)
        ss += __shfl_xor_sync(0xffffffffu, ss, off);
    __shared__ float red[8];
    if ((t & 31) == 0) red[t >> 5] = ss;
    __syncthreads();
    float tot = red[0]+red[1]+red[2]+red[3]+red[4]+red[5]+red[6]+red[7];
    float rstd = rsqrtf(tot * (1.f / 1024.f) + 1e-6f);
    float4 wv = ((const float4*)w)[t];
    __half2* o = (__half2*)(y + (size_t)row * 1024);
    o[2 * t]     = __floats2half2_rn(v.x * rstd * wv.x, v.y * rstd * wv.y);
    o[2 * t + 1] = __floats2half2_rn(v.z * rstd * wv.z, v.w * rstd * wv.w);
}

// -------------------- liquid + PLIF scan -> fp16 ------------------------------
__global__ void scan_kernel(const float* __restrict__ Ab,
                            const float* __restrict__ Bb,
                            const float* __restrict__ log_tau,
                            const float* __restrict__ thr,
                            __half* __restrict__ spike_in) {
    const int gid = blockIdx.x * blockDim.x + threadIdx.x;  // 0..8191
    const int d = gid & (Ddim - 1);
    const int b = gid >> 10;
    const float pdec = expf(-expf(-log_tau[d]));
    const float omp  = 1.f - pdec;
    const float th   = thr[d];
    size_t idx = (size_t)b * Tdim * Ddim + d;
    float h = 0.f, v = 0.f;
    #pragma unroll 4
    for (int t = 0; t < Tdim; ++t, idx += Ddim) {
        float a  = Ab[idx];
        float bb = Bb[idx];
        h = tanhf(fmaf(a, h, bb));
        float vpre = fmaf(pdec, v, omp * h);
        float s = (vpre > th) ? 1.f : 0.f;
        v = vpre - s * th;
        spike_in[idx] = __float2half_rn(s + h);
    }
}

// ==================== fp16 fused (dual-)GEMM ================================
// out[m,n] = sum_k A[m,k]*W{1,2}[n,k]; CTA 128x128; warp tile 32x32 (dual).
// EPI 0: out1(f32)=exp(-softplus(c1+b1)*exp(Alog[n])),
//        out2(f32)=softplus(c1+b1)*(c2+b2)
// EPI 1: out1(f32) = extra + (c1+b1)*sigmoid(c2+b2)
// EPI 2: out1(f16) = silu(c1)*c2
// EPI 3: out1(f32) = extra + c1                       (non-dual)
template <bool DUAL, int EPI>
__global__ void __launch_bounds__(NTHREADS, 1)
gemm_h(const __half* __restrict__ A,
       const __half* __restrict__ W1,
       const __half* __restrict__ W2,
       void* __restrict__ out1v,
       void* __restrict__ out2v,
       const float* __restrict__ bias1,
       const float* __restrict__ bias2,
       const float* __restrict__ extra,
       int K, int N) {
    extern __shared__ char smem[];
    const uint32_t stg0 = (smem_u32(smem) + 1023u) & ~1023u;

    const int tid  = threadIdx.x;
    const int warp = tid >> 5;
    const int lane = tid & 31;
    const int wm = warp >> 2;
    const int wn = warp & 3;
    const int bm = blockIdx.y * 128;
    const int bn = blockIdx.x * 128;

    const char* Arow = (const char*)(A  + (size_t)bm * K);
    const char* B1   = (const char*)(W1 + (size_t)bn * K);
    const char* B2   = DUAL ? (const char*)(W2 + (size_t)bn * K) : B1;
    const size_t rs = (size_t)K * 2;

    const int NCHUNK = DUAL ? 3072 : 2048;
    auto load_stage = [&](int s, int kt) {
        const uint32_t sb = stg0 + s * STAGE_BYTES;
        const size_t ko = (size_t)kt * 128;        // bytes (64 halves)
        #pragma unroll
        for (int i = 0; i < 6; ++i) {
            const int c = tid + i * NTHREADS;
            if (c >= NCHUNK) break;
            const int mat = c >> 10;
            const int idx = c & 1023;
            const int row = idx >> 3;
            const int off = idx & 7;
            const char* src = (mat == 0) ? (Arow + row * rs + ko + off * 16)
                            : (mat == 1) ? (B1   + row * rs + ko + off * 16)
                                         : (B2   + row * rs + ko + off * 16);
            cp16(sb + mat * STAGE_A + SWZ(row * 128 + off * 16), src);
        }
        cp_commit();
    };

    float acc1[2][4][4];
    float acc2[2][4][4];
    #pragma unroll
    for (int i = 0; i < 2; ++i)
        #pragma unroll
        for (int j = 0; j < 4; ++j)
            #pragma unroll
            for (int k = 0; k < 4; ++k) { acc1[i][j][k] = 0.f; acc2[i][j][k] = 0.f; }

    const int NK = K / 64;
    load_stage(0, 0);
    load_stage(1, 1);
    load_stage(2, 2);

    const int mi  = lane >> 3;
    const int rin = lane & 7;
    const int a_mrow = wm * 32 + (mi & 1) * 8 + rin;
    const int a_koff = (mi >> 1) * 16;             // bytes
    const int b_nrow = wn * 32 + (mi >> 1) * 8 + rin;
    const int b_koff = (mi & 1) * 16;

    for (int kt = 0; kt < NK; ++kt) {
        const int s = kt % NSTG;
        const int rem = NK - 1 - kt;
        if (rem >= 2)      cp_wait<2>();
        else if (rem == 1) cp_wait<1>();
        else               cp_wait<0>();
        __syncthreads();

        const uint32_t sA  = stg0 + s * STAGE_BYTES;
        const uint32_t sB1 = sA + STAGE_A;
        const uint32_t sB2 = sA + 2 * STAGE_A;

        #pragma unroll
        for (int ks = 0; ks < 4; ++ks) {           // 4 x k16 (32B chunks)
            uint32_t a[2][4];
            #pragma unroll
            for (int mb = 0; mb < 2; ++mb)
                ldsm4(a[mb], sA + SWZ((a_mrow + mb * 16) * 128 + ks * 32 + a_koff));

            uint32_t bf1[4][2], bf2[4][2];
            #pragma unroll
            for (int nbp = 0; nbp < 2; ++nbp) {
                uint32_t t[4];
                ldsm4(t, sB1 + SWZ((b_nrow + nbp * 16) * 128 + ks * 32 + b_koff));
                bf1[2*nbp][0] = t[0]; bf1[2*nbp][1] = t[1];
                bf1[2*nbp+1][0] = t[2]; bf1[2*nbp+1][1] = t[3];
                if (DUAL) {
                    ldsm4(t, sB2 + SWZ((b_nrow + nbp * 16) * 128 + ks * 32 + b_koff));
                    bf2[2*nbp][0] = t[0]; bf2[2*nbp][1] = t[1];
                    bf2[2*nbp+1][0] = t[2]; bf2[2*nbp+1][1] = t[3];
                }
            }

            #pragma unroll
            for (int mb = 0; mb < 2; ++mb)
                #pragma unroll
                for (int nb = 0; nb < 4; ++nb) {
                    mma16h(acc1[mb][nb], a[mb], bf1[nb]);
                    if (DUAL) mma16h(acc2[mb][nb], a[mb], bf2[nb]);
                }
        }
        // 4 buffers, 3 in flight: buffer written below was last read at kt-1,
        // ordered by the barrier above -> no second barrier needed.
        if (kt + 3 < NK) load_stage((kt + 3) % NSTG, kt + 3);
    }

    // ------------------------------- epilogue -------------------------------
    const int r_base = bm + wm * 32 + (lane >> 2);
    const int c_base = bn + wn * 32 + (lane & 3) * 2;
    float* out1 = (float*)out1v;
    float* out2 = (float*)out2v;
    __half* out1h = (__half*)out1v;

    #pragma unroll
    for (int mb = 0; mb < 2; ++mb) {
        #pragma unroll
        for (int nb = 0; nb < 4; ++nb) {
            const int r0 = r_base + mb * 16;
            const int r1 = r0 + 8;
            const int cc = c_base + nb * 8;
            const size_t o0 = (size_t)r0 * N + cc;
            const size_t o1 = (size_t)r1 * N + cc;
            const float* d1 = acc1[mb][nb];
            const float* d2 = acc2[mb][nb];

            if (EPI == 0) {
                float b1a = __ldg(bias1 + cc), b1b = __ldg(bias1 + cc + 1);
                float b2a = __ldg(bias2 + cc), b2b = __ldg(bias2 + cc + 1);
                float ea  = expf(__ldg(extra + cc));
                float eb  = expf(__ldg(extra + cc + 1));
                float dl;
                dl = softplusf(d1[0] + b1a); float v00 = expf(-dl * ea);
                float w00 = dl * (d2[0] + b2a);
                dl = softplusf(d1[1] + b1b); float v01 = expf(-dl * eb);
                float w01 = dl * (d2[1] + b2b);
                dl = softplusf(d1[2] + b1a); float v10 = expf(-dl * ea);
                float w10 = dl * (d2[2] + b2a);
                dl = softplusf(d1[3] + b1b); float v11 = expf(-dl * eb);
                float w11 = dl * (d2[3] + b2b);
                *(float2*)(out1 + o0) = make_float2(v00, v01);
                *(float2*)(out1 + o1) = make_float2(v10, v11);
                *(float2*)(out2 + o0) = make_float2(w00, w01);
                *(float2*)(out2 + o1) = make_float2(w10, w11);
            } else if (EPI == 1) {
                float b1a = __ldg(bias1 + cc), b1b = __ldg(bias1 + cc + 1);
                float b2a = __ldg(bias2 + cc), b2b = __ldg(bias2 + cc + 1);
                float2 xa = *(const float2*)(extra + o0);
                float2 xb = *(const float2*)(extra + o1);
                float v00 = xa.x + (d1[0] + b1a) * sigmoidf(d2[0] + b2a);
                float v01 = xa.y + (d1[1] + b1b) * sigmoidf(d2[1] + b2b);
                float v10 = xb.x + (d1[2] + b1a) * sigmoidf(d2[2] + b2a);
                float v11 = xb.y + (d1[3] + b1b) * sigmoidf(d2[3] + b2b);
                *(float2*)(out1 + o0) = make_float2(v00, v01);
                *(float2*)(out1 + o1) = make_float2(v10, v11);
            } else if (EPI == 2) {
                float v00 = d1[0] * sigmoidf(d1[0]) * d2[0];
                float v01 = d1[1] * sigmoidf(d1[1]) * d2[1];
                float v10 = d1[2] * sigmoidf(d1[2]) * d2[2];
                float v11 = d1[3] * sigmoidf(d1[3]) * d2[3];
                *(__half2*)(out1h + o0) = __floats2half2_rn(v00, v01);
                *(__half2*)(out1h + o1) = __floats2half2_rn(v10, v11);
            } else {  // EPI == 3
                float2 xa = *(const float2*)(extra + o0);
                float2 xb = *(const float2*)(extra + o1);
                *(float2*)(out1 + o0) = make_float2(xa.x + d1[0], xa.y + d1[1]);
                *(float2*)(out1 + o1) = make_float2(xb.x + d1[2], xb.y + d1[3]);
            }
        }
    }
}

// ---------------------------------------------------------------------------
extern "C" void kernel_launch(void* const* d_in, const int* in_sizes, int n_in,
                              void* d_out, int out_size) {
    const float* x       = (const float*)d_in[0];
    const float* rms_w1  = (const float*)d_in[1];
    const float* rms_w2  = (const float*)d_in[2];
    const float* delta_w = (const float*)d_in[3];
    const float* delta_b = (const float*)d_in[4];
    const float* b_w     = (const float*)d_in[5];
    const float* b_b     = (const float*)d_in[6];
    const float* A_log   = (const float*)d_in[7];
    const float* log_tau = (const float*)d_in[8];
    const float* plif_thr= (const float*)d_in[9];
    const float* syn_w   = (const float*)d_in[10];
    const float* syn_b   = (const float*)d_in[11];
    const float* gate_w  = (const float*)d_in[12];
    const float* gate_b  = (const float*)d_in[13];
    const float* ffn_g_w = (const float*)d_in[14];
    const float* ffn_u_w = (const float*)d_in[15];
    const float* ffn_d_w = (const float*)d_in[16];
    float* out = (float*)d_out;

    float *Aa, *Bb, *x1;
    __half *y1, *sp, *y2, *act, *wh;
    cudaGetSymbolAddress((void**)&Aa,  g_Aa);
    cudaGetSymbolAddress((void**)&Bb,  g_Bb);
    cudaGetSymbolAddress((void**)&x1,  g_x1);
    cudaGetSymbolAddress((void**)&y1,  g_y1);
    cudaGetSymbolAddress((void**)&sp,  g_sp);
    cudaGetSymbolAddress((void**)&y2,  g_y2);
    cudaGetSymbolAddress((void**)&act, g_act);
    cudaGetSymbolAddress((void**)&wh,  g_wh);

    cudaFuncSetAttribute(gemm_h<true, 0>, cudaFuncAttributeMaxDynamicSharedMemorySize, SMEM_BYTES);
    cudaFuncSetAttribute(gemm_h<true, 1>, cudaFuncAttributeMaxDynamicSharedMemorySize, SMEM_BYTES);
    cudaFuncSetAttribute(gemm_h<true, 2>, cudaFuncAttributeMaxDynamicSharedMemorySize, SMEM_BYTES);
    cudaFuncSetAttribute(gemm_h<false, 3>, cudaFuncAttributeMaxDynamicSharedMemorySize, SMEM_BYTES);

    const int M = Mdim, D = Ddim, F = Fdim;
    const int MEG = 1024 * 1024;

    __half* wh_dw   = wh + 0 * MEG;
    __half* wh_bw   = wh + 1 * MEG;
    __half* wh_syn  = wh + 2 * MEG;
    __half* wh_gate = wh + 3 * MEG;
    __half* wh_g    = wh + 4 * MEG;
    __half* wh_u    = wh + 8 * MEG;
    __half* wh_d    = wh + 12 * MEG;
    w2h_kernel<<<MEG / 1024, 256>>>((const float4*)delta_w, (__half2*)wh_dw);
    w2h_kernel<<<MEG / 1024, 256>>>((const float4*)b_w,     (__half2*)wh_bw);
    w2h_kernel<<<MEG / 1024, 256>>>((const float4*)syn_w,   (__half2*)wh_syn);
    w2h_kernel<<<MEG / 1024, 256>>>((const float4*)gate_w,  (__half2*)wh_gate);
    w2h_kernel<<<4 * MEG / 1024, 256>>>((const float4*)ffn_g_w, (__half2*)wh_g);
    w2h_kernel<<<4 * MEG / 1024, 256>>>((const float4*)ffn_u_w, (__half2*)wh_u);
    w2h_kernel<<<4 * MEG / 1024, 256>>>((const float4*)ffn_d_w, (__half2*)wh_d);

    // 1) y1 = rmsnorm(x) in fp16
    rmsnorm_kernel<<<M, 256>>>(x, rms_w1, y1);

    // 2) A, bvec (dual fp16 GEMM, fused softplus/exp epilogue)
    dim3 g1(D / 128, M / 128);
    gemm_h<true, 0><<<g1, NTHREADS, SMEM_BYTES>>>(y1, wh_dw, wh_bw, Aa, Bb,
                                                  delta_b, b_b, A_log, D, D);
    // 3) scan -> spike_in (fp16)
    scan_kernel<<<64, 128>>>(Aa, Bb, log_tau, plif_thr, sp);

    // 4) x1 = x + syn*sigmoid(gate)
    gemm_h<true, 1><<<g1, NTHREADS, SMEM_BYTES>>>(sp, wh_syn, wh_gate, x1, nullptr,
                                                  syn_b, gate_b, x, D, D);
    // 5) y2 = rmsnorm(x1) in fp16
    rmsnorm_kernel<<<M, 256>>>(x1, rms_w2, y2);

    // 6) act = silu(y2@g^T)*(y2@u^T) in fp16
    dim3 g3(F / 128, M / 128);
    gemm_h<true, 2><<<g3, NTHREADS, SMEM_BYTES>>>(y2, wh_g, wh_u, act, nullptr,
                                                  nullptr, nullptr, nullptr, D, F);
    // 7) out = x1 + act@d^T
    dim3 g4(D / 128, M / 128);
    gemm_h<false, 3><<<g4, NTHREADS, SMEM_BYTES>>>(act, wh_d, nullptr, out, nullptr,
                                                   nullptr, nullptr, x1, F, D);
}